// round 1
// baseline (speedup 1.0000x reference)
#include <cuda_runtime.h>
#include <cuda_bf16.h>
#include <math.h>

// ---------------- problem constants ----------------
#define S_    1024
#define B_    4
#define D_    1024
#define H_    16
#define HD_   64
#define DFF_  4096
#define NTOK  (S_*B_)        // 4096 rows

// ---------------- scratch (device globals; allocation-free) ----------------
__device__ float g_src2 [NTOK*D_];
__device__ float g_qk   [NTOK*D_];
__device__ float g_q    [NTOK*D_];
__device__ float g_k    [NTOK*D_];
__device__ float g_v    [NTOK*D_];
__device__ float g_ctx  [NTOK*D_];
__device__ float g_x    [NTOK*D_];
__device__ float g_src2b[NTOK*D_];
__device__ float g_h    [NTOK*DFF_];
__device__ float g_scores[(long long)B_*H_*S_*S_];
__device__ float g_win  [3*D_*D_];
__device__ float g_wout [D_*D_];
__device__ float g_w1q  [DFF_*D_];
__device__ float g_w2q  [D_*DFF_];

// ---------------- reductions ----------------
__device__ __forceinline__ float blockReduceSum(float val) {
    __shared__ float sh[8];
    int lane = threadIdx.x & 31, w = threadIdx.x >> 5;
    #pragma unroll
    for (int o = 16; o > 0; o >>= 1) val += __shfl_xor_sync(0xffffffffu, val, o);
    __syncthreads();                  // protect sh from a previous call
    if (lane == 0) sh[w] = val;
    __syncthreads();
    if (w == 0) {
        float v = (lane < 8) ? sh[lane] : 0.0f;
        #pragma unroll
        for (int o = 4; o > 0; o >>= 1) v += __shfl_xor_sync(0xffffffffu, v, o);
        if (lane == 0) sh[0] = v;
    }
    __syncthreads();
    return sh[0];
}

__device__ __forceinline__ float blockReduceMax(float val) {
    __shared__ float sh[8];
    int lane = threadIdx.x & 31, w = threadIdx.x >> 5;
    #pragma unroll
    for (int o = 16; o > 0; o >>= 1) val = fmaxf(val, __shfl_xor_sync(0xffffffffu, val, o));
    __syncthreads();
    if (lane == 0) sh[w] = val;
    __syncthreads();
    if (w == 0) {
        float v = (lane < 8) ? sh[lane] : -3.4e38f;
        #pragma unroll
        for (int o = 4; o > 0; o >>= 1) v = fmaxf(v, __shfl_xor_sync(0xffffffffu, v, o));
        if (lane == 0) sh[0] = v;
    }
    __syncthreads();
    return sh[0];
}

// ---------------- LSQ forward quant: round(clamp(w/a,-8,7))*a ----------------
__global__ void quant_kernel(const float4* __restrict__ w,
                             const float*  __restrict__ alpha,
                             float4* __restrict__ o, int n4) {
    int i = blockIdx.x * blockDim.x + threadIdx.x;
    if (i >= n4) return;
    float a = alpha[0];
    float4 v = w[i];
    v.x = rintf(fminf(fmaxf(v.x / a, -8.0f), 7.0f)) * a;
    v.y = rintf(fminf(fmaxf(v.y / a, -8.0f), 7.0f)) * a;
    v.z = rintf(fminf(fmaxf(v.z / a, -8.0f), 7.0f)) * a;
    v.w = rintf(fminf(fmaxf(v.w / a, -8.0f), 7.0f)) * a;
    o[i] = v;
}

// ---------------- layernorm (optionally also emits out+pos) ----------------
__global__ void ln_kernel(const float* __restrict__ x, const float* __restrict__ pos,
                          const float* __restrict__ gam, const float* __restrict__ bet,
                          float* __restrict__ out, float* __restrict__ outqk) {
    long long row = blockIdx.x;
    const float* xr = x + row * D_;
    int t = threadIdx.x;                    // 256 threads, 4 elems each
    float v[4];
    float s = 0.0f;
    #pragma unroll
    for (int j = 0; j < 4; j++) { v[j] = xr[t + j * 256]; s += v[j]; }
    float m = blockReduceSum(s) * (1.0f / D_);
    float s2 = 0.0f;
    #pragma unroll
    for (int j = 0; j < 4; j++) { float d = v[j] - m; s2 += d * d; }
    float var = blockReduceSum(s2) * (1.0f / D_);
    float rs = rsqrtf(var + 1e-5f);
    #pragma unroll
    for (int j = 0; j < 4; j++) {
        int c = t + j * 256;
        float y = (v[j] - m) * rs * gam[c] + bet[c];
        out[row * D_ + c] = y;
        if (outqk) outqk[row * D_ + c] = y + pos[row * D_ + c];
    }
}

// ---------------- row softmax over 1024 cols ----------------
__global__ void softmax1024(float* __restrict__ p) {
    long long row = blockIdx.x;
    float* x = p + row * 1024;
    int t = threadIdx.x;
    float v[4];
    float mx = -3.4e38f;
    #pragma unroll
    for (int j = 0; j < 4; j++) { v[j] = x[t + j * 256]; mx = fmaxf(mx, v[j]); }
    mx = blockReduceMax(mx);
    float s = 0.0f;
    #pragma unroll
    for (int j = 0; j < 4; j++) { v[j] = expf(v[j] - mx); s += v[j]; }
    s = blockReduceSum(s);
    float inv = 1.0f / s;
    #pragma unroll
    for (int j = 0; j < 4; j++) x[t + j * 256] = v[j] * inv;
}

// ---------------- 128x128x8 fp32 GEMM: C = act(scale*A@B^T + bias + resid) ----
// Batched over gridDim.z: z -> (bz = z/nh, hz = z%nh), per-matrix offsets.
// Requires M,N % 128 == 0, K % 8 == 0, and 16B-aligned bases/ld (all true here).
__global__ void __launch_bounds__(256)
gemm_abt128(int M, int N, int K,
            const float* __restrict__ A, int lda, long long aB, long long aH,
            const float* __restrict__ Bw, int ldb, long long bB, long long bH,
            float* __restrict__ C, int ldc, long long cB, long long cH,
            const float* __restrict__ bias,
            const float* __restrict__ resid, int ldr,
            float scale, int relu, int nh) {
    __shared__ float As[8][128];
    __shared__ float Bs[8][128];
    int z = blockIdx.z, bz = z / nh, hz = z % nh;
    A  += bz * aB + hz * aH;
    Bw += bz * bB + hz * bH;
    C  += bz * cB + hz * cH;
    int bm = blockIdx.y * 128, bn = blockIdx.x * 128;
    int tid = threadIdx.x;
    int tx = tid & 15, ty = tid >> 4;
    int la = tid * 4;
    int ar = la >> 3, ac = la & 7;          // tile row 0..127, k col {0,4}
    const float* Aptr = A  + (long long)(bm + ar) * lda + ac;
    const float* Bptr = Bw + (long long)(bn + ar) * ldb + ac;
    float acc[8][8];
    #pragma unroll
    for (int i = 0; i < 8; i++)
        #pragma unroll
        for (int j = 0; j < 8; j++) acc[i][j] = 0.0f;

    for (int k0 = 0; k0 < K; k0 += 8) {
        float4 av = *(const float4*)(Aptr + k0);
        float4 bv = *(const float4*)(Bptr + k0);
        __syncthreads();
        As[ac + 0][ar] = av.x; As[ac + 1][ar] = av.y;
        As[ac + 2][ar] = av.z; As[ac + 3][ar] = av.w;
        Bs[ac + 0][ar] = bv.x; Bs[ac + 1][ar] = bv.y;
        Bs[ac + 2][ar] = bv.z; Bs[ac + 3][ar] = bv.w;
        __syncthreads();
        #pragma unroll
        for (int kk = 0; kk < 8; kk++) {
            float a[8], b[8];
            *(float4*)(a)     = *(const float4*)&As[kk][ty * 4];
            *(float4*)(a + 4) = *(const float4*)&As[kk][64 + ty * 4];
            *(float4*)(b)     = *(const float4*)&Bs[kk][tx * 4];
            *(float4*)(b + 4) = *(const float4*)&Bs[kk][64 + tx * 4];
            #pragma unroll
            for (int i = 0; i < 8; i++)
                #pragma unroll
                for (int j = 0; j < 8; j++) acc[i][j] += a[i] * b[j];
        }
    }
    #pragma unroll
    for (int i = 0; i < 8; i++) {
        int row = bm + ((i < 4) ? (ty * 4 + i) : (64 + ty * 4 + i - 4));
        #pragma unroll
        for (int j = 0; j < 8; j++) {
            int col = bn + ((j < 4) ? (tx * 4 + j) : (64 + tx * 4 + j - 4));
            float v = acc[i][j] * scale;
            if (bias)  v += bias[col];
            if (resid) v += resid[(long long)row * ldr + col];
            if (relu)  v = fmaxf(v, 0.0f);
            C[(long long)row * ldc + col] = v;
        }
    }
}

// ---------------- ctx GEMM: C[M,64] = A[M,K] @ B[K,64] (batched per head) ----
__global__ void __launch_bounds__(256)
gemm_ab64(int M, int K,
          const float* __restrict__ A, int lda, long long aB, long long aH,
          const float* __restrict__ Bm, int ldb, long long bB, long long bH,
          float* __restrict__ C, int ldc, long long cB, long long cH, int nh) {
    __shared__ float As[16][64];
    __shared__ float Bs[16][64];
    int z = blockIdx.z, bz = z / nh, hz = z % nh;
    A  += bz * aB + hz * aH;
    Bm += bz * bB + hz * bH;
    C  += bz * cB + hz * cH;
    int bm = blockIdx.y * 64;
    int tid = threadIdx.x, tx = tid & 15, ty = tid >> 4;
    int la = tid * 4;
    int ar = la >> 4, ac = la & 15;   // A: row 0..63, k {0,4,8,12}
    int br = la >> 6, bc = la & 63;   // B: k row 0..15, n col
    float acc[4][4];
    #pragma unroll
    for (int i = 0; i < 4; i++)
        #pragma unroll
        for (int j = 0; j < 4; j++) acc[i][j] = 0.0f;

    for (int k0 = 0; k0 < K; k0 += 16) {
        float4 av = *(const float4*)(A  + (long long)(bm + ar) * lda + k0 + ac);
        float4 bv = *(const float4*)(Bm + (long long)(k0 + br) * ldb + bc);
        __syncthreads();
        As[ac + 0][ar] = av.x; As[ac + 1][ar] = av.y;
        As[ac + 2][ar] = av.z; As[ac + 3][ar] = av.w;
        *(float4*)&Bs[br][bc] = bv;
        __syncthreads();
        #pragma unroll
        for (int kk = 0; kk < 16; kk++) {
            float a[4], b[4];
            *(float4*)a = *(const float4*)&As[kk][ty * 4];
            *(float4*)b = *(const float4*)&Bs[kk][tx * 4];
            #pragma unroll
            for (int i = 0; i < 4; i++)
                #pragma unroll
                for (int j = 0; j < 4; j++) acc[i][j] += a[i] * b[j];
        }
    }
    #pragma unroll
    for (int i = 0; i < 4; i++)
        #pragma unroll
        for (int j = 0; j < 4; j++)
            C[(long long)(bm + ty * 4 + i) * ldc + tx * 4 + j] = acc[i][j];
}

// ---------------- host launch ----------------
template <typename T>
static float* symaddr(T& sym) { void* p = nullptr; cudaGetSymbolAddress(&p, sym); return (float*)p; }

extern "C" void kernel_launch(void* const* d_in, const int* in_sizes, int n_in,
                              void* d_out, int out_size) {
    const float* src       = (const float*)d_in[0];
    const float* pos       = (const float*)d_in[1];
    const float* in_proj_w = (const float*)d_in[2];
    const float* alpha_in  = (const float*)d_in[3];
    const float* out_proj_w= (const float*)d_in[4];
    const float* alpha_out = (const float*)d_in[5];
    const float* w1        = (const float*)d_in[6];
    const float* b1        = (const float*)d_in[7];
    const float* alpha1    = (const float*)d_in[8];
    const float* w2        = (const float*)d_in[9];
    const float* b2        = (const float*)d_in[10];
    const float* alpha2    = (const float*)d_in[11];
    const float* ln1g      = (const float*)d_in[12];
    const float* ln1b      = (const float*)d_in[13];
    const float* ln2g      = (const float*)d_in[14];
    const float* ln2b      = (const float*)d_in[15];
    float* out = (float*)d_out;

    float* p_src2  = symaddr(g_src2);
    float* p_qk    = symaddr(g_qk);
    float* p_q     = symaddr(g_q);
    float* p_k     = symaddr(g_k);
    float* p_v     = symaddr(g_v);
    float* p_ctx   = symaddr(g_ctx);
    float* p_x     = symaddr(g_x);
    float* p_src2b = symaddr(g_src2b);
    float* p_h     = symaddr(g_h);
    float* p_sc    = symaddr(g_scores);
    float* p_win   = symaddr(g_win);
    float* p_wout  = symaddr(g_wout);
    float* p_w1q   = symaddr(g_w1q);
    float* p_w2q   = symaddr(g_w2q);

    // 1) LSQ quantize all weights
    {
        int n4;
        n4 = (3 * D_ * D_) / 4;
        quant_kernel<<<(n4 + 255) / 256, 256>>>((const float4*)in_proj_w, alpha_in, (float4*)p_win, n4);
        n4 = (D_ * D_) / 4;
        quant_kernel<<<(n4 + 255) / 256, 256>>>((const float4*)out_proj_w, alpha_out, (float4*)p_wout, n4);
        n4 = (DFF_ * D_) / 4;
        quant_kernel<<<(n4 + 255) / 256, 256>>>((const float4*)w1, alpha1, (float4*)p_w1q, n4);
        n4 = (D_ * DFF_) / 4;
        quant_kernel<<<(n4 + 255) / 256, 256>>>((const float4*)w2, alpha2, (float4*)p_w2q, n4);
    }

    // 2) LN1 -> src2, qk = src2 + pos
    ln_kernel<<<NTOK, 256>>>(src, pos, ln1g, ln1b, p_src2, p_qk);

    // 3) q/k/v projections (q scaled by 1/sqrt(64)=0.125)
    gemm_abt128<<<dim3(8, 32, 1), 256>>>(NTOK, D_, D_,
        p_qk, D_, 0, 0,   p_win, D_, 0, 0,            p_q, D_, 0, 0,
        nullptr, nullptr, 0, 0.125f, 0, 1);
    gemm_abt128<<<dim3(8, 32, 1), 256>>>(NTOK, D_, D_,
        p_qk, D_, 0, 0,   p_win + D_ * D_, D_, 0, 0,  p_k, D_, 0, 0,
        nullptr, nullptr, 0, 1.0f, 0, 1);
    gemm_abt128<<<dim3(8, 32, 1), 256>>>(NTOK, D_, D_,
        p_src2, D_, 0, 0, p_win + 2 * D_ * D_, D_, 0, 0, p_v, D_, 0, 0,
        nullptr, nullptr, 0, 1.0f, 0, 1);

    // 4) scores[b,h] = q @ k^T  (batched over 64 (b,h); row stride B*D)
    gemm_abt128<<<dim3(8, 8, B_ * H_), 256>>>(S_, S_, HD_,
        p_q, B_ * D_, D_, HD_,
        p_k, B_ * D_, D_, HD_,
        p_sc, S_, (long long)H_ * S_ * S_, (long long)S_ * S_,
        nullptr, nullptr, 0, 1.0f, 0, H_);

    // 5) softmax over last dim
    softmax1024<<<B_ * H_ * S_, 256>>>(p_sc);

    // 6) ctx[b,h] = attn @ v   (N=64 per head)
    gemm_ab64<<<dim3(1, S_ / 64, B_ * H_), 256>>>(S_, S_,
        p_sc, S_, (long long)H_ * S_ * S_, (long long)S_ * S_,
        p_v, B_ * D_, D_, HD_,
        p_ctx, B_ * D_, D_, HD_, H_);

    // 7) attn_out + residual -> x
    gemm_abt128<<<dim3(8, 32, 1), 256>>>(NTOK, D_, D_,
        p_ctx, D_, 0, 0, p_wout, D_, 0, 0, p_x, D_, 0, 0,
        nullptr, src, D_, 1.0f, 0, 1);

    // 8) LN2
    ln_kernel<<<NTOK, 256>>>(p_x, nullptr, ln2g, ln2b, p_src2b, nullptr);

    // 9) FFN1: h = relu(src2b @ w1^T + b1)
    gemm_abt128<<<dim3(32, 32, 1), 256>>>(NTOK, DFF_, D_,
        p_src2b, D_, 0, 0, p_w1q, D_, 0, 0, p_h, DFF_, 0, 0,
        b1, nullptr, 0, 1.0f, 1, 1);

    // 10) FFN2 + residual -> out
    gemm_abt128<<<dim3(8, 32, 1), 256>>>(NTOK, D_, DFF_,
        p_h, DFF_, 0, 0, p_w2q, DFF_, 0, 0, out, D_, 0, 0,
        b2, p_x, D_, 1.0f, 0, 1);
}

// round 3
// speedup vs baseline: 1.8468x; 1.8468x over previous
#include <cuda_runtime.h>
#include <cuda_bf16.h>
#include <math.h>

// ---------------- problem constants ----------------
#define S_    1024
#define B_    4
#define D_    1024
#define H_    16
#define HD_   64
#define DFF_  4096
#define NTOK  (S_*B_)        // 4096 rows

typedef unsigned int uint;
typedef unsigned short ushort;

// ---------------- scratch (device globals; allocation-free) ----------------
// split-interleaved bf16 activations: [row][2*K]  (even = hi, odd = lo)
__device__ __nv_bfloat16 g_qk2   [NTOK*2*D_];    // split(LN1(src)+pos)
__device__ __nv_bfloat16 g_sv2   [NTOK*2*D_];    // split(LN1(src))
__device__ __nv_bfloat16 g_ctx2  [NTOK*2*D_];    // split(ctx)
__device__ __nv_bfloat16 g_s2b2  [NTOK*2*D_];    // split(LN2(x))
__device__ __nv_bfloat16 g_h2    [NTOK*2*DFF_];  // split(relu ffn1)
// duplicated integer-code weights: [n][2*K] bf16 (pairs of identical codes)
__device__ __nv_bfloat16 g_win2  [3*D_*2*D_];
__device__ __nv_bfloat16 g_wout2 [D_*2*D_];
__device__ __nv_bfloat16 g_w12   [DFF_*2*D_];
__device__ __nv_bfloat16 g_w22   [D_*2*DFF_];
// fp32 intermediates
__device__ float g_qkout[NTOK*2048];             // q (cols 0..1023) || k (1024..2047)
__device__ float g_v    [NTOK*D_];
__device__ float g_x    [NTOK*D_];
__device__ float g_scores[(long long)B_*H_*S_*S_];

// ---------------- helpers ----------------
__device__ __forceinline__ ushort f2bf_bits(float x) {
    __nv_bfloat16 h = __float2bfloat16(x);
    return *(ushort*)&h;
}
__device__ __forceinline__ uint pack_split(float v) {
    ushort hi = f2bf_bits(v);
    __nv_bfloat16 hb = *(__nv_bfloat16*)&hi;
    float lo = v - __bfloat162float(hb);
    ushort lb = f2bf_bits(lo);
    return (uint)hi | ((uint)lb << 16);
}

__device__ __forceinline__ float blockReduceSum(float val) {
    __shared__ float sh[8];
    int lane = threadIdx.x & 31, w = threadIdx.x >> 5;
    #pragma unroll
    for (int o = 16; o > 0; o >>= 1) val += __shfl_xor_sync(0xffffffffu, val, o);
    __syncthreads();
    if (lane == 0) sh[w] = val;
    __syncthreads();
    if (w == 0) {
        float v = (lane < 8) ? sh[lane] : 0.0f;
        #pragma unroll
        for (int o = 4; o > 0; o >>= 1) v += __shfl_xor_sync(0xffffffffu, v, o);
        if (lane == 0) sh[0] = v;
    }
    __syncthreads();
    return sh[0];
}
__device__ __forceinline__ float blockReduceMax(float val) {
    __shared__ float sh[8];
    int lane = threadIdx.x & 31, w = threadIdx.x >> 5;
    #pragma unroll
    for (int o = 16; o > 0; o >>= 1) val = fmaxf(val, __shfl_xor_sync(0xffffffffu, val, o));
    __syncthreads();
    if (lane == 0) sh[w] = val;
    __syncthreads();
    if (w == 0) {
        float v = (lane < 8) ? sh[lane] : -3.4e38f;
        #pragma unroll
        for (int o = 4; o > 0; o >>= 1) v = fmaxf(v, __shfl_xor_sync(0xffffffffu, v, o));
        if (lane == 0) sh[0] = v;
    }
    __syncthreads();
    return sh[0];
}

// ---------------- quantize weights to duplicated integer codes ------------
// in: w [N][K] f32, out: [N][2K] bf16 with out[n][2k]=out[n][2k+1]=rint(clamp(w/a,-8,7))
__global__ void quant_dup(const float4* __restrict__ w, const float* __restrict__ alpha,
                          uint4* __restrict__ out, int n4) {
    int i = blockIdx.x * blockDim.x + threadIdx.x;
    if (i >= n4) return;
    float inv = 1.0f / alpha[0];
    float4 v = w[i];
    uint4 o;
    ushort b0 = f2bf_bits(rintf(fminf(fmaxf(v.x * inv, -8.0f), 7.0f)));
    ushort b1 = f2bf_bits(rintf(fminf(fmaxf(v.y * inv, -8.0f), 7.0f)));
    ushort b2 = f2bf_bits(rintf(fminf(fmaxf(v.z * inv, -8.0f), 7.0f)));
    ushort b3 = f2bf_bits(rintf(fminf(fmaxf(v.w * inv, -8.0f), 7.0f)));
    o.x = (uint)b0 * 0x10001u;
    o.y = (uint)b1 * 0x10001u;
    o.z = (uint)b2 * 0x10001u;
    o.w = (uint)b3 * 0x10001u;
    out[i] = o;
}

// ---------------- layernorm -> split bf16 outputs --------------------------
// out2a = split(y), out2b = split(y + pos)   (either may be null)
__global__ void ln_kernel(const float* __restrict__ x, const float* __restrict__ pos,
                          const float* __restrict__ gam, const float* __restrict__ bet,
                          uint* __restrict__ out2a, uint* __restrict__ out2b) {
    long long row = blockIdx.x;
    const float* xr = x + row * D_;
    int t = threadIdx.x;
    float v[4];
    float s = 0.0f;
    #pragma unroll
    for (int j = 0; j < 4; j++) { v[j] = xr[t + j * 256]; s += v[j]; }
    float m = blockReduceSum(s) * (1.0f / D_);
    float s2 = 0.0f;
    #pragma unroll
    for (int j = 0; j < 4; j++) { float d = v[j] - m; s2 += d * d; }
    float var = blockReduceSum(s2) * (1.0f / D_);
    float rs = rsqrtf(var + 1e-5f);
    #pragma unroll
    for (int j = 0; j < 4; j++) {
        int c = t + j * 256;
        float y = (v[j] - m) * rs * gam[c] + bet[c];
        if (out2a) out2a[row * D_ + c] = pack_split(y);
        if (out2b) out2b[row * D_ + c] = pack_split(y + pos[row * D_ + c]);
    }
}

// ---------------- row softmax over 1024 cols ----------------
__global__ void softmax1024(float* __restrict__ p) {
    long long row = blockIdx.x;
    float* x = p + row * 1024;
    int t = threadIdx.x;
    float v[4];
    float mx = -3.4e38f;
    #pragma unroll
    for (int j = 0; j < 4; j++) { v[j] = x[t + j * 256]; mx = fmaxf(mx, v[j]); }
    mx = blockReduceMax(mx);
    float s = 0.0f;
    #pragma unroll
    for (int j = 0; j < 4; j++) { v[j] = expf(v[j] - mx); s += v[j]; }
    s = blockReduceSum(s);
    float inv = 1.0f / s;
    #pragma unroll
    for (int j = 0; j < 4; j++) x[t + j * 256] = v[j] * inv;
}

// ================= bf16 tensor-core GEMM (mma.sync m16n8k16) ===============
// C[M,N] = act( alpha * (A2[M,K2] @ B2[N,K2]^T) + bias + resid )
// A2/B2 are bf16 (split-interleaved activations x duplicated weight codes).
// Output: fp32 (outF) and/or split-interleaved bf16 (out2 at [row][2N]).
#define PITCH 40   // bf16 elems per smem row

__device__ __forceinline__ void cp16(void* smem, const void* gmem) {
    uint s = (uint)__cvta_generic_to_shared(smem);
    asm volatile("cp.async.cg.shared.global [%0], [%1], 16;\n" :: "r"(s), "l"(gmem));
}
__device__ __forceinline__ void cp_commit() { asm volatile("cp.async.commit_group;\n"); }
template <int N> __device__ __forceinline__ void cp_wait() {
    asm volatile("cp.async.wait_group %0;\n" :: "n"(N));
}

__global__ void __launch_bounds__(256)
gemm_bf16(int M, int N, int K2,
          const __nv_bfloat16* __restrict__ A, const __nv_bfloat16* __restrict__ Bw,
          const float* __restrict__ alpha, const float* __restrict__ bias,
          const float* __restrict__ resid,
          float* __restrict__ outF, uint* __restrict__ out2, int relu) {
    __shared__ __nv_bfloat16 As[2][128][PITCH];
    __shared__ __nv_bfloat16 Bs[2][128][PITCH];

    int bm = blockIdx.y * 128, bn = blockIdx.x * 128;
    int tid  = threadIdx.x;
    int lane = tid & 31, wid = tid >> 5;
    int wm = wid >> 2, wn = wid & 3;           // 2x4 warp grid: warp tile 64x32
    int g  = lane >> 2, tg = lane & 3;

    int lrow = tid >> 1, lcol = (tid & 1) * 16;  // load mapping: 2 thr/row, 16 bf16 each
    const __nv_bfloat16* Ag = A  + (long long)(bm + lrow) * K2 + lcol;
    const __nv_bfloat16* Bg = Bw + (long long)(bn + lrow) * K2 + lcol;

    float acc[4][4][4];
    #pragma unroll
    for (int i = 0; i < 4; i++)
        #pragma unroll
        for (int j = 0; j < 4; j++)
            #pragma unroll
            for (int r = 0; r < 4; r++) acc[i][j][r] = 0.0f;

    int nk = K2 / 32;
    // prefetch stage 0
    cp16(&As[0][lrow][lcol],     Ag);
    cp16(&As[0][lrow][lcol + 8], Ag + 8);
    cp16(&Bs[0][lrow][lcol],     Bg);
    cp16(&Bs[0][lrow][lcol + 8], Bg + 8);
    cp_commit();

    for (int kt = 0; kt < nk; kt++) {
        if (kt + 1 < nk) {
            int st = (kt + 1) & 1;
            long long off = (long long)(kt + 1) * 32;
            cp16(&As[st][lrow][lcol],     Ag + off);
            cp16(&As[st][lrow][lcol + 8], Ag + off + 8);
            cp16(&Bs[st][lrow][lcol],     Bg + off);
            cp16(&Bs[st][lrow][lcol + 8], Bg + off + 8);
            cp_commit();
            cp_wait<1>();
        } else {
            cp_wait<0>();
        }
        __syncthreads();
        int st = kt & 1;
        #pragma unroll
        for (int ks = 0; ks < 2; ks++) {
            int kb = ks * 16;
            uint a[4][4], b[4][2];
            #pragma unroll
            for (int mi = 0; mi < 4; mi++) {
                int rb = wm * 64 + mi * 16;
                a[mi][0] = *(const uint*)&As[st][rb + g    ][kb + tg * 2];
                a[mi][1] = *(const uint*)&As[st][rb + g + 8][kb + tg * 2];
                a[mi][2] = *(const uint*)&As[st][rb + g    ][kb + tg * 2 + 8];
                a[mi][3] = *(const uint*)&As[st][rb + g + 8][kb + tg * 2 + 8];
            }
            #pragma unroll
            for (int ni = 0; ni < 4; ni++) {
                int nb = wn * 32 + ni * 8;
                b[ni][0] = *(const uint*)&Bs[st][nb + g][kb + tg * 2];
                b[ni][1] = *(const uint*)&Bs[st][nb + g][kb + tg * 2 + 8];
            }
            #pragma unroll
            for (int mi = 0; mi < 4; mi++)
                #pragma unroll
                for (int ni = 0; ni < 4; ni++) {
                    asm volatile(
                        "mma.sync.aligned.m16n8k16.row.col.f32.bf16.bf16.f32 "
                        "{%0,%1,%2,%3}, {%4,%5,%6,%7}, {%8,%9}, {%0,%1,%2,%3};\n"
                        : "+f"(acc[mi][ni][0]), "+f"(acc[mi][ni][1]),
                          "+f"(acc[mi][ni][2]), "+f"(acc[mi][ni][3])
                        : "r"(a[mi][0]), "r"(a[mi][1]), "r"(a[mi][2]), "r"(a[mi][3]),
                          "r"(b[ni][0]), "r"(b[ni][1]));
                }
        }
        __syncthreads();
    }

    float alp = alpha ? alpha[0] : 1.0f;
    #pragma unroll
    for (int mi = 0; mi < 4; mi++) {
        #pragma unroll
        for (int ni = 0; ni < 4; ni++) {
            #pragma unroll
            for (int r = 0; r < 4; r++) {
                int row = bm + wm * 64 + mi * 16 + g + (r >= 2 ? 8 : 0);
                int col = bn + wn * 32 + ni * 8 + tg * 2 + (r & 1);
                float v = acc[mi][ni][r] * alp;
                if (bias)  v += bias[col];
                if (resid) v += resid[(long long)row * N + col];
                if (relu)  v = fmaxf(v, 0.0f);
                if (outF)  outF[(long long)row * N + col] = v;
                if (out2)  out2[(long long)row * N + col] = pack_split(v);
            }
        }
    }
}

// ---------------- fp32 128x128x8 GEMM: C = scale*A@B^T (attention scores) --
__global__ void __launch_bounds__(256)
gemm_abt128(int M, int N, int K,
            const float* __restrict__ A, int lda, long long aB, long long aH,
            const float* __restrict__ Bw, int ldb, long long bB, long long bH,
            float* __restrict__ C, int ldc, long long cB, long long cH,
            float scale, int nh) {
    __shared__ float As[8][128];
    __shared__ float Bs[8][128];
    int z = blockIdx.z, bz = z / nh, hz = z % nh;
    A  += bz * aB + hz * aH;
    Bw += bz * bB + hz * bH;
    C  += bz * cB + hz * cH;
    int bm = blockIdx.y * 128, bn = blockIdx.x * 128;
    int tid = threadIdx.x;
    int tx = tid & 15, ty = tid >> 4;
    int la = tid * 4;
    int ar = la >> 3, ac = la & 7;
    const float* Aptr = A  + (long long)(bm + ar) * lda + ac;
    const float* Bptr = Bw + (long long)(bn + ar) * ldb + ac;
    float acc[8][8];
    #pragma unroll
    for (int i = 0; i < 8; i++)
        #pragma unroll
        for (int j = 0; j < 8; j++) acc[i][j] = 0.0f;

    for (int k0 = 0; k0 < K; k0 += 8) {
        float4 av = *(const float4*)(Aptr + k0);
        float4 bv = *(const float4*)(Bptr + k0);
        __syncthreads();
        As[ac + 0][ar] = av.x; As[ac + 1][ar] = av.y;
        As[ac + 2][ar] = av.z; As[ac + 3][ar] = av.w;
        Bs[ac + 0][ar] = bv.x; Bs[ac + 1][ar] = bv.y;
        Bs[ac + 2][ar] = bv.z; Bs[ac + 3][ar] = bv.w;
        __syncthreads();
        #pragma unroll
        for (int kk = 0; kk < 8; kk++) {
            float a[8], b[8];
            *(float4*)(a)     = *(const float4*)&As[kk][ty * 4];
            *(float4*)(a + 4) = *(const float4*)&As[kk][64 + ty * 4];
            *(float4*)(b)     = *(const float4*)&Bs[kk][tx * 4];
            *(float4*)(b + 4) = *(const float4*)&Bs[kk][64 + tx * 4];
            #pragma unroll
            for (int i = 0; i < 8; i++)
                #pragma unroll
                for (int j = 0; j < 8; j++) acc[i][j] += a[i] * b[j];
        }
    }
    #pragma unroll
    for (int i = 0; i < 8; i++) {
        int row = bm + ((i < 4) ? (ty * 4 + i) : (64 + ty * 4 + i - 4));
        #pragma unroll
        for (int j = 0; j < 8; j++) {
            int col = bn + ((j < 4) ? (tx * 4 + j) : (64 + tx * 4 + j - 4));
            C[(long long)row * ldc + col] = acc[i][j] * scale;
        }
    }
}

// ---------------- ctx GEMM: C[M,64] = A @ B, output split bf16 -------------
__global__ void __launch_bounds__(256)
gemm_ab64(int M, int K,
          const float* __restrict__ A, int lda, long long aB, long long aH,
          const float* __restrict__ Bm, int ldb, long long bB, long long bH,
          uint* __restrict__ C, int ldc, long long cB, long long cH, int nh) {
    __shared__ float As[16][64];
    __shared__ float Bs[16][64];
    int z = blockIdx.z, bz = z / nh, hz = z % nh;
    A  += bz * aB + hz * aH;
    Bm += bz * bB + hz * bH;
    C  += bz * cB + hz * cH;
    int bm = blockIdx.y * 64;
    int tid = threadIdx.x, tx = tid & 15, ty = tid >> 4;
    int la = tid * 4;
    int ar = la >> 4, ac = la & 15;
    int br = la >> 6, bc = la & 63;
    float acc[4][4];
    #pragma unroll
    for (int i = 0; i < 4; i++)
        #pragma unroll
        for (int j = 0; j < 4; j++) acc[i][j] = 0.0f;

    for (int k0 = 0; k0 < K; k0 += 16) {
        float4 av = *(const float4*)(A  + (long long)(bm + ar) * lda + k0 + ac);
        float4 bv = *(const float4*)(Bm + (long long)(k0 + br) * ldb + bc);
        __syncthreads();
        As[ac + 0][ar] = av.x; As[ac + 1][ar] = av.y;
        As[ac + 2][ar] = av.z; As[ac + 3][ar] = av.w;
        *(float4*)&Bs[br][bc] = bv;
        __syncthreads();
        #pragma unroll
        for (int kk = 0; kk < 16; kk++) {
            float a[4], b[4];
            *(float4*)a = *(const float4*)&As[kk][ty * 4];
            *(float4*)b = *(const float4*)&Bs[kk][tx * 4];
            #pragma unroll
            for (int i = 0; i < 4; i++)
                #pragma unroll
                for (int j = 0; j < 4; j++) acc[i][j] += a[i] * b[j];
        }
    }
    #pragma unroll
    for (int i = 0; i < 4; i++)
        #pragma unroll
        for (int j = 0; j < 4; j++)
            C[(long long)(bm + ty * 4 + i) * ldc + (tx * 4 + j)] = pack_split(acc[i][j]);
}

// ---------------- host launch ----------------
template <typename T>
static void* symaddr(T& sym) { void* p = nullptr; cudaGetSymbolAddress(&p, sym); return p; }

extern "C" void kernel_launch(void* const* d_in, const int* in_sizes, int n_in,
                              void* d_out, int out_size) {
    const float* src       = (const float*)d_in[0];
    const float* pos       = (const float*)d_in[1];
    const float* in_proj_w = (const float*)d_in[2];
    const float* alpha_in  = (const float*)d_in[3];
    const float* out_proj_w= (const float*)d_in[4];
    const float* alpha_out = (const float*)d_in[5];
    const float* w1        = (const float*)d_in[6];
    const float* b1        = (const float*)d_in[7];
    const float* alpha1    = (const float*)d_in[8];
    const float* w2        = (const float*)d_in[9];
    const float* b2        = (const float*)d_in[10];
    const float* alpha2    = (const float*)d_in[11];
    const float* ln1g      = (const float*)d_in[12];
    const float* ln1b      = (const float*)d_in[13];
    const float* ln2g      = (const float*)d_in[14];
    const float* ln2b      = (const float*)d_in[15];
    float* out = (float*)d_out;

    __nv_bfloat16* p_qk2  = (__nv_bfloat16*)symaddr(g_qk2);
    __nv_bfloat16* p_sv2  = (__nv_bfloat16*)symaddr(g_sv2);
    __nv_bfloat16* p_ctx2 = (__nv_bfloat16*)symaddr(g_ctx2);
    __nv_bfloat16* p_s2b2 = (__nv_bfloat16*)symaddr(g_s2b2);
    __nv_bfloat16* p_h2   = (__nv_bfloat16*)symaddr(g_h2);
    __nv_bfloat16* p_win2 = (__nv_bfloat16*)symaddr(g_win2);
    __nv_bfloat16* p_wout2= (__nv_bfloat16*)symaddr(g_wout2);
    __nv_bfloat16* p_w12  = (__nv_bfloat16*)symaddr(g_w12);
    __nv_bfloat16* p_w22  = (__nv_bfloat16*)symaddr(g_w22);
    float* p_qkout = (float*)symaddr(g_qkout);
    float* p_v     = (float*)symaddr(g_v);
    float* p_x     = (float*)symaddr(g_x);
    float* p_sc    = (float*)symaddr(g_scores);

    // 1) weights -> duplicated integer codes (bf16, exact)
    {
        int n4;
        n4 = (3 * D_ * D_) / 4;
        quant_dup<<<(n4 + 255) / 256, 256>>>((const float4*)in_proj_w, alpha_in, (uint4*)p_win2, n4);
        n4 = (D_ * D_) / 4;
        quant_dup<<<(n4 + 255) / 256, 256>>>((const float4*)out_proj_w, alpha_out, (uint4*)p_wout2, n4);
        n4 = (DFF_ * D_) / 4;
        quant_dup<<<(n4 + 255) / 256, 256>>>((const float4*)w1, alpha1, (uint4*)p_w12, n4);
        n4 = (D_ * DFF_) / 4;
        quant_dup<<<(n4 + 255) / 256, 256>>>((const float4*)w2, alpha2, (uint4*)p_w22, n4);
    }

    // 2) LN1 -> split(src2) and split(src2+pos)
    ln_kernel<<<NTOK, 256>>>(src, pos, ln1g, ln1b, (uint*)p_sv2, (uint*)p_qk2);

    // 3) [q||k] = qk2 @ win2[0:2048)^T * alpha_in  (M=4096, N=2048, K2=2048)
    gemm_bf16<<<dim3(16, 32), 256>>>(NTOK, 2048, 2048,
        p_qk2, p_win2, alpha_in, nullptr, nullptr, p_qkout, nullptr, 0);
    //    v = sv2 @ win2[2048:3072)^T * alpha_in
    gemm_bf16<<<dim3(8, 32), 256>>>(NTOK, 1024, 2048,
        p_sv2, p_win2 + (long long)2048 * 2048, alpha_in, nullptr, nullptr, p_v, nullptr, 0);

    // 4) scores = 0.125 * q @ k^T  (batched over 64 (b,h))
    gemm_abt128<<<dim3(8, 8, B_ * H_), 256>>>(S_, S_, HD_,
        p_qkout, B_ * 2048, 2048, 64,
        p_qkout + 1024, B_ * 2048, 2048, 64,
        p_sc, S_, (long long)H_ * S_ * S_, (long long)S_ * S_,
        0.125f, H_);

    // 5) softmax
    softmax1024<<<B_ * H_ * S_, 256>>>(p_sc);

    // 6) ctx = attn @ v  -> split bf16 interleaved into ctx2
    gemm_ab64<<<dim3(1, S_ / 64, B_ * H_), 256>>>(S_, S_,
        p_sc, S_, (long long)H_ * S_ * S_, (long long)S_ * S_,
        p_v, B_ * D_, D_, HD_,
        (uint*)p_ctx2, B_ * D_, D_, HD_, H_);

    // 7) x = ctx2 @ wout2^T * alpha_out + src
    gemm_bf16<<<dim3(8, 32), 256>>>(NTOK, 1024, 2048,
        p_ctx2, p_wout2, alpha_out, nullptr, src, p_x, nullptr, 0);

    // 8) LN2 -> split(src2b)
    ln_kernel<<<NTOK, 256>>>(p_x, nullptr, ln2g, ln2b, (uint*)p_s2b2, nullptr);

    // 9) h2 = split(relu(s2b2 @ w12^T * alpha1 + b1))
    gemm_bf16<<<dim3(32, 32), 256>>>(NTOK, 4096, 2048,
        p_s2b2, p_w12, alpha1, b1, nullptr, nullptr, (uint*)p_h2, 1);

    // 10) out = h2 @ w22^T * alpha2 + b2 + x
    gemm_bf16<<<dim3(8, 32), 256>>>(NTOK, 1024, 8192,
        p_h2, p_w22, alpha2, b2, p_x, out, nullptr, 0);
}

// round 5
// speedup vs baseline: 2.2480x; 1.2172x over previous
#include <cuda_runtime.h>
#include <cuda_bf16.h>
#include <math.h>

// ---------------- problem constants ----------------
#define S_    1024
#define B_    4
#define D_    1024
#define H_    16
#define HD_   64
#define DFF_  4096
#define NTOK  (S_*B_)        // 4096 rows

typedef unsigned int uint;
typedef unsigned short ushort;

// ---------------- scratch (device globals; allocation-free) ----------------
__device__ __nv_bfloat16 g_qk2   [NTOK*2*D_];    // split(LN1(src)+pos)
__device__ __nv_bfloat16 g_sv2   [NTOK*2*D_];    // split(LN1(src))
__device__ __nv_bfloat16 g_ctx2  [NTOK*2*D_];    // split(ctx)  (written by flash)
__device__ __nv_bfloat16 g_s2b2  [NTOK*2*D_];    // split(LN2(x))
__device__ __nv_bfloat16 g_h2    [NTOK*2*DFF_];  // split(relu ffn1)
__device__ __nv_bfloat16 g_win2  [3*D_*2*D_];
__device__ __nv_bfloat16 g_wout2 [D_*2*D_];
__device__ __nv_bfloat16 g_w12   [DFF_*2*D_];
__device__ __nv_bfloat16 g_w22   [D_*2*DFF_];
__device__ uint  g_qkp  [NTOK*2048];             // packed split q (cols 0..1023) | k (1024..2047)
__device__ uint  g_vp   [NTOK*1024];             // packed split v
__device__ float g_x    [NTOK*D_];

// ---------------- helpers ----------------
__device__ __forceinline__ ushort f2bf_bits(float x) {
    __nv_bfloat16 h = __float2bfloat16(x);
    return *(ushort*)&h;
}
__device__ __forceinline__ uint pack_split(float v) {
    ushort hi = f2bf_bits(v);
    __nv_bfloat16 hb = *(__nv_bfloat16*)&hi;
    float lo = v - __bfloat162float(hb);
    ushort lb = f2bf_bits(lo);
    return (uint)hi | ((uint)lb << 16);
}
// pack two floats as bf16x2: low half = lo_elem
__device__ __forceinline__ uint bf2pack(float lo_elem, float hi_elem) {
    uint r;
    asm("cvt.rn.bf16x2.f32 %0, %1, %2;" : "=r"(r) : "f"(hi_elem), "f"(lo_elem));
    return r;
}
// fast exp on FMA pipe (no MUFU, no F2I). Valid for x <= ~0; exp(-126*ln2)->~0.
__device__ __forceinline__ float fexp(float x) {
    float y = fmaxf(x * 1.4426950408889634f, -126.0f);
    float z = y + 12582912.0f;           // RNE integer capture
    float n = z - 12582912.0f;
    float t = (y - n) * 0.6931471805599453f;
    float p = 1.9841269841e-4f;
    p = fmaf(p, t, 1.3888888889e-3f);
    p = fmaf(p, t, 8.3333333333e-3f);
    p = fmaf(p, t, 4.1666666667e-2f);
    p = fmaf(p, t, 1.6666666667e-1f);
    p = fmaf(p, t, 0.5f);
    p = fmaf(p, t, 1.0f);
    p = fmaf(p, t, 1.0f);
    int sc = (__float_as_int(z) - 0x4B400000 + 127) << 23;
    return p * __int_as_float(sc);
}

__device__ __forceinline__ float blockReduceSum(float val) {
    __shared__ float sh[8];
    int lane = threadIdx.x & 31, w = threadIdx.x >> 5;
    #pragma unroll
    for (int o = 16; o > 0; o >>= 1) val += __shfl_xor_sync(0xffffffffu, val, o);
    __syncthreads();
    if (lane == 0) sh[w] = val;
    __syncthreads();
    if (w == 0) {
        float v = (lane < 8) ? sh[lane] : 0.0f;
        #pragma unroll
        for (int o = 4; o > 0; o >>= 1) v += __shfl_xor_sync(0xffffffffu, v, o);
        if (lane == 0) sh[0] = v;
    }
    __syncthreads();
    return sh[0];
}

// ---------------- quantize weights to duplicated integer codes ------------
__global__ void quant_dup(const float4* __restrict__ w, const float* __restrict__ alpha,
                          uint4* __restrict__ out, int n4) {
    int i = blockIdx.x * blockDim.x + threadIdx.x;
    if (i >= n4) return;
    float inv = 1.0f / alpha[0];
    float4 v = w[i];
    uint4 o;
    o.x = (uint)f2bf_bits(rintf(fminf(fmaxf(v.x * inv, -8.0f), 7.0f))) * 0x10001u;
    o.y = (uint)f2bf_bits(rintf(fminf(fmaxf(v.y * inv, -8.0f), 7.0f))) * 0x10001u;
    o.z = (uint)f2bf_bits(rintf(fminf(fmaxf(v.z * inv, -8.0f), 7.0f))) * 0x10001u;
    o.w = (uint)f2bf_bits(rintf(fminf(fmaxf(v.w * inv, -8.0f), 7.0f))) * 0x10001u;
    out[i] = o;
}

// ---------------- layernorm -> split bf16 outputs --------------------------
__global__ void ln_kernel(const float* __restrict__ x, const float* __restrict__ pos,
                          const float* __restrict__ gam, const float* __restrict__ bet,
                          uint* __restrict__ out2a, uint* __restrict__ out2b) {
    long long row = blockIdx.x;
    const float* xr = x + row * D_;
    int t = threadIdx.x;
    float v[4];
    float s = 0.0f;
    #pragma unroll
    for (int j = 0; j < 4; j++) { v[j] = xr[t + j * 256]; s += v[j]; }
    float m = blockReduceSum(s) * (1.0f / D_);
    float s2 = 0.0f;
    #pragma unroll
    for (int j = 0; j < 4; j++) { float d = v[j] - m; s2 += d * d; }
    float var = blockReduceSum(s2) * (1.0f / D_);
    float rs = rsqrtf(var + 1e-5f);
    #pragma unroll
    for (int j = 0; j < 4; j++) {
        int c = t + j * 256;
        float y = (v[j] - m) * rs * gam[c] + bet[c];
        if (out2a) out2a[row * D_ + c] = pack_split(y);
        if (out2b) out2b[row * D_ + c] = pack_split(y + pos[row * D_ + c]);
    }
}

// ================= bf16 tensor-core GEMM (mma.sync m16n8k16) ===============
#define PITCH 40

__device__ __forceinline__ void cp16(void* smem, const void* gmem) {
    uint s = (uint)__cvta_generic_to_shared(smem);
    asm volatile("cp.async.cg.shared.global [%0], [%1], 16;\n" :: "r"(s), "l"(gmem));
}
__device__ __forceinline__ void cp_commit() { asm volatile("cp.async.commit_group;\n"); }
template <int N> __device__ __forceinline__ void cp_wait() {
    asm volatile("cp.async.wait_group %0;\n" :: "n"(N));
}
__device__ __forceinline__ void mma16816(float* c, uint a0, uint a1, uint a2, uint a3,
                                         uint b0, uint b1) {
    asm volatile(
        "mma.sync.aligned.m16n8k16.row.col.f32.bf16.bf16.f32 "
        "{%0,%1,%2,%3}, {%4,%5,%6,%7}, {%8,%9}, {%0,%1,%2,%3};\n"
        : "+f"(c[0]), "+f"(c[1]), "+f"(c[2]), "+f"(c[3])
        : "r"(a0), "r"(a1), "r"(a2), "r"(a3), "r"(b0), "r"(b1));
}

__global__ void __launch_bounds__(256)
gemm_bf16(int M, int N, int K2,
          const __nv_bfloat16* __restrict__ A, const __nv_bfloat16* __restrict__ Bw,
          const float* __restrict__ alpha, const float* __restrict__ bias,
          const float* __restrict__ resid,
          float* __restrict__ outF, uint* __restrict__ out2, int relu) {
    __shared__ __nv_bfloat16 As[2][128][PITCH];
    __shared__ __nv_bfloat16 Bs[2][128][PITCH];

    int bm = blockIdx.y * 128, bn = blockIdx.x * 128;
    int tid  = threadIdx.x;
    int lane = tid & 31, wid = tid >> 5;
    int wm = wid >> 2, wn = wid & 3;
    int g  = lane >> 2, tg = lane & 3;

    int lrow = tid >> 1, lcol = (tid & 1) * 16;
    const __nv_bfloat16* Ag = A  + (long long)(bm + lrow) * K2 + lcol;
    const __nv_bfloat16* Bg = Bw + (long long)(bn + lrow) * K2 + lcol;

    float acc[4][4][4];
    #pragma unroll
    for (int i = 0; i < 4; i++)
        #pragma unroll
        for (int j = 0; j < 4; j++)
            #pragma unroll
            for (int r = 0; r < 4; r++) acc[i][j][r] = 0.0f;

    int nk = K2 / 32;
    cp16(&As[0][lrow][lcol],     Ag);
    cp16(&As[0][lrow][lcol + 8], Ag + 8);
    cp16(&Bs[0][lrow][lcol],     Bg);
    cp16(&Bs[0][lrow][lcol + 8], Bg + 8);
    cp_commit();

    for (int kt = 0; kt < nk; kt++) {
        if (kt + 1 < nk) {
            int st = (kt + 1) & 1;
            long long off = (long long)(kt + 1) * 32;
            cp16(&As[st][lrow][lcol],     Ag + off);
            cp16(&As[st][lrow][lcol + 8], Ag + off + 8);
            cp16(&Bs[st][lrow][lcol],     Bg + off);
            cp16(&Bs[st][lrow][lcol + 8], Bg + off + 8);
            cp_commit();
            cp_wait<1>();
        } else {
            cp_wait<0>();
        }
        __syncthreads();
        int st = kt & 1;
        #pragma unroll
        for (int ks = 0; ks < 2; ks++) {
            int kb = ks * 16;
            uint a[4][4], b[4][2];
            #pragma unroll
            for (int mi = 0; mi < 4; mi++) {
                int rb = wm * 64 + mi * 16;
                a[mi][0] = *(const uint*)&As[st][rb + g    ][kb + tg * 2];
                a[mi][1] = *(const uint*)&As[st][rb + g + 8][kb + tg * 2];
                a[mi][2] = *(const uint*)&As[st][rb + g    ][kb + tg * 2 + 8];
                a[mi][3] = *(const uint*)&As[st][rb + g + 8][kb + tg * 2 + 8];
            }
            #pragma unroll
            for (int ni = 0; ni < 4; ni++) {
                int nb = wn * 32 + ni * 8;
                b[ni][0] = *(const uint*)&Bs[st][nb + g][kb + tg * 2];
                b[ni][1] = *(const uint*)&Bs[st][nb + g][kb + tg * 2 + 8];
            }
            #pragma unroll
            for (int mi = 0; mi < 4; mi++)
                #pragma unroll
                for (int ni = 0; ni < 4; ni++)
                    mma16816(acc[mi][ni], a[mi][0], a[mi][1], a[mi][2], a[mi][3],
                             b[ni][0], b[ni][1]);
        }
        __syncthreads();
    }

    float alp = alpha ? alpha[0] : 1.0f;
    #pragma unroll
    for (int mi = 0; mi < 4; mi++) {
        #pragma unroll
        for (int ni = 0; ni < 4; ni++) {
            #pragma unroll
            for (int r = 0; r < 4; r++) {
                int row = bm + wm * 64 + mi * 16 + g + (r >= 2 ? 8 : 0);
                int col = bn + wn * 32 + ni * 8 + tg * 2 + (r & 1);
                float v = acc[mi][ni][r] * alp;
                if (bias)  v += bias[col];
                if (resid) v += resid[(long long)row * N + col];
                if (relu)  v = fmaxf(v, 0.0f);
                if (outF)  outF[(long long)row * N + col] = v;
                if (out2)  out2[(long long)row * N + col] = pack_split(v);
            }
        }
    }
}

// ======================= fused flash attention =============================
// grid (8 q-tiles, 64 b*h), 256 threads. One (b,h): Q[1024,64] (packed split),
// K[1024,64], V[1024,64]. 3-term hi/lo split on both QK^T and P@V.
#define QKP 200   // bf16 pitch for Qs/Ks (100 words, !=0 mod 32)
#define VTP 136   // bf16 pitch for V^T tiles (68 words)
#define FLASH_SMEM ((2*128*QKP + 2*64*VTP) * 2)

__global__ void __launch_bounds__(256, 1)
flash_attn(const uint* __restrict__ qkp, const uint* __restrict__ vp,
           uint* __restrict__ ctx2) {
    extern __shared__ char smraw[];
    uint* Qw  = (uint*)smraw;                 // [128][100] words
    uint* Kw  = Qw + 128 * (QKP / 2);
    uint* Vhw = Kw + 128 * (QKP / 2);         // [64][68] words
    uint* Vlw = Vhw + 64 * (VTP / 2);

    int qt = blockIdx.x, bh = blockIdx.y;
    int b = bh >> 4, h = bh & 15;
    int tid = threadIdx.x, lane = tid & 31, w = tid >> 5;
    int g = lane >> 2, tg = lane & 3;

    // ---- load Q tile: scale by 0.125 (exact), layout [q_hi | q_lo | q_hi] ----
    {
        const uint* qb = qkp + h * 64;
        __nv_bfloat162 sc = __float2bfloat162_rn(0.125f);
        #pragma unroll 4
        for (int i = tid; i < 128 * 32; i += 256) {
            int r = i >> 5, c = i & 31;
            long long tok = (long long)(qt * 128 + r) * B_ + b;
            uint u0 = qb[tok * 2048 + 2 * c];
            uint u1 = qb[tok * 2048 + 2 * c + 1];
            __nv_bfloat162 s0 = __hmul2(*(__nv_bfloat162*)&u0, sc);
            __nv_bfloat162 s1 = __hmul2(*(__nv_bfloat162*)&u1, sc);
            uint v0 = *(uint*)&s0, v1 = *(uint*)&s1;
            uint hihi = __byte_perm(v0, v1, 0x5410);
            uint lolo = __byte_perm(v0, v1, 0x7632);
            int base = r * 100 + c;
            Qw[base] = hihi; Qw[base + 32] = lolo; Qw[base + 64] = hihi;
        }
    }

    float m0 = -1e30f, m1 = -1e30f, l0 = 0.0f, l1 = 0.0f;
    float o[8][4];
    #pragma unroll
    for (int i = 0; i < 8; i++)
        #pragma unroll
        for (int r = 0; r < 4; r++) o[i][r] = 0.0f;

    int arow  = (w * 16 + g) * 100;
    int arow8 = arow + 800;

    for (int t0 = 0; t0 < S_; t0 += 128) {
        if (t0 > 0) __syncthreads();
        // ---- load K tile: layout [k_hi | k_hi | k_lo] ----
        {
            const uint* kb = qkp + 1024 + h * 64;
            #pragma unroll 4
            for (int i = tid; i < 128 * 32; i += 256) {
                int r = i >> 5, c = i & 31;
                long long tok = (long long)(t0 + r) * B_ + b;
                uint u0 = kb[tok * 2048 + 2 * c];
                uint u1 = kb[tok * 2048 + 2 * c + 1];
                uint hihi = __byte_perm(u0, u1, 0x5410);
                uint lolo = __byte_perm(u0, u1, 0x7632);
                int base = r * 100 + c;
                Kw[base] = hihi; Kw[base + 32] = hihi; Kw[base + 64] = lolo;
            }
        }
        // ---- load V tile transposed: Vh[d][t], Vl[d][t] ----
        {
            const uint* vb = vp + h * 64;
            #pragma unroll 4
            for (int i = tid; i < 64 * 64; i += 256) {
                int tp = i >> 6, d = i & 63;
                long long tok0 = (long long)(t0 + tp * 2) * B_ + b;
                uint u0 = vb[tok0 * 1024 + d];
                uint u1 = vb[(tok0 + B_) * 1024 + d];
                Vhw[d * 68 + tp] = __byte_perm(u0, u1, 0x5410);
                Vlw[d * 68 + tp] = __byte_perm(u0, u1, 0x7632);
            }
        }
        __syncthreads();

        // ---- S-tile = Q @ K^T  (warp rows w*16..w*16+15, 128 cols) ----
        float s[16][4];
        #pragma unroll
        for (int nf = 0; nf < 16; nf++)
            #pragma unroll
            for (int r = 0; r < 4; r++) s[nf][r] = 0.0f;

        #pragma unroll
        for (int ks = 0; ks < 12; ks++) {
            int kb = ks * 8 + tg;
            uint a0 = Qw[arow + kb], a1 = Qw[arow8 + kb];
            uint a2 = Qw[arow + kb + 4], a3 = Qw[arow8 + kb + 4];
            #pragma unroll
            for (int nf = 0; nf < 16; nf++) {
                int brow = (nf * 8 + g) * 100 + kb;
                mma16816(s[nf], a0, a1, a2, a3, Kw[brow], Kw[brow + 4]);
            }
        }

        // ---- online softmax update ----
        float mt0 = -1e30f, mt1 = -1e30f;
        #pragma unroll
        for (int nf = 0; nf < 16; nf++) {
            mt0 = fmaxf(mt0, fmaxf(s[nf][0], s[nf][1]));
            mt1 = fmaxf(mt1, fmaxf(s[nf][2], s[nf][3]));
        }
        mt0 = fmaxf(mt0, __shfl_xor_sync(0xffffffffu, mt0, 1));
        mt0 = fmaxf(mt0, __shfl_xor_sync(0xffffffffu, mt0, 2));
        mt1 = fmaxf(mt1, __shfl_xor_sync(0xffffffffu, mt1, 1));
        mt1 = fmaxf(mt1, __shfl_xor_sync(0xffffffffu, mt1, 2));
        float mn0 = fmaxf(m0, mt0), mn1 = fmaxf(m1, mt1);
        float c0 = fexp(m0 - mn0), c1 = fexp(m1 - mn1);
        l0 *= c0; l1 *= c1;
        #pragma unroll
        for (int nf = 0; nf < 8; nf++) {
            o[nf][0] *= c0; o[nf][1] *= c0; o[nf][2] *= c1; o[nf][3] *= c1;
        }
        float rs0 = 0.0f, rs1 = 0.0f;
        #pragma unroll
        for (int nf = 0; nf < 16; nf++) {
            s[nf][0] = fexp(s[nf][0] - mn0); s[nf][1] = fexp(s[nf][1] - mn0);
            s[nf][2] = fexp(s[nf][2] - mn1); s[nf][3] = fexp(s[nf][3] - mn1);
            rs0 += s[nf][0] + s[nf][1];
            rs1 += s[nf][2] + s[nf][3];
        }
        rs0 += __shfl_xor_sync(0xffffffffu, rs0, 1);
        rs0 += __shfl_xor_sync(0xffffffffu, rs0, 2);
        rs1 += __shfl_xor_sync(0xffffffffu, rs1, 1);
        rs1 += __shfl_xor_sync(0xffffffffu, rs1, 2);
        l0 += rs0; l1 += rs1; m0 = mn0; m1 = mn1;

        // ---- O += P @ V  (3-term split; reuse S frags as A frags) ----
        #pragma unroll
        for (int kt = 0; kt < 8; kt++) {
            float p00 = s[2*kt][0],   p01 = s[2*kt][1],   p02 = s[2*kt][2],   p03 = s[2*kt][3];
            float p10 = s[2*kt+1][0], p11 = s[2*kt+1][1], p12 = s[2*kt+1][2], p13 = s[2*kt+1][3];
            uint u00 = __float_as_uint(p00), u01 = __float_as_uint(p01);
            uint u02 = __float_as_uint(p02), u03 = __float_as_uint(p03);
            uint u10 = __float_as_uint(p10), u11 = __float_as_uint(p11);
            uint u12 = __float_as_uint(p12), u13 = __float_as_uint(p13);
            // hi = truncated-to-bf16 (exact split)
            uint ah0 = __byte_perm(u00, u01, 0x7632);
            uint ah1 = __byte_perm(u02, u03, 0x7632);
            uint ah2 = __byte_perm(u10, u11, 0x7632);
            uint ah3 = __byte_perm(u12, u13, 0x7632);
            uint al0 = bf2pack(p00 - __uint_as_float(u00 & 0xFFFF0000u),
                               p01 - __uint_as_float(u01 & 0xFFFF0000u));
            uint al1 = bf2pack(p02 - __uint_as_float(u02 & 0xFFFF0000u),
                               p03 - __uint_as_float(u03 & 0xFFFF0000u));
            uint al2 = bf2pack(p10 - __uint_as_float(u10 & 0xFFFF0000u),
                               p11 - __uint_as_float(u11 & 0xFFFF0000u));
            uint al3 = bf2pack(p12 - __uint_as_float(u12 & 0xFFFF0000u),
                               p13 - __uint_as_float(u13 & 0xFFFF0000u));
            #pragma unroll
            for (int nf = 0; nf < 8; nf++) {
                int brow = (nf * 8 + g) * 68 + kt * 8 + tg;
                uint bh0 = Vhw[brow], bh1 = Vhw[brow + 4];
                uint bl0 = Vlw[brow], bl1 = Vlw[brow + 4];
                mma16816(o[nf], ah0, ah1, ah2, ah3, bh0, bh1);
                mma16816(o[nf], al0, al1, al2, al3, bh0, bh1);
                mma16816(o[nf], ah0, ah1, ah2, ah3, bl0, bl1);
            }
        }
    }

    // ---- epilogue: ctx = O / l, write packed split ----
    float i0 = 1.0f / l0, i1 = 1.0f / l1;
    long long tok0 = (long long)(qt * 128 + w * 16 + g) * B_ + b;
    long long tok1 = tok0 + 8LL * B_;
    #pragma unroll
    for (int nf = 0; nf < 8; nf++) {
        int col = h * 64 + nf * 8 + tg * 2;
        ctx2[tok0 * 1024 + col]     = pack_split(o[nf][0] * i0);
        ctx2[tok0 * 1024 + col + 1] = pack_split(o[nf][1] * i0);
        ctx2[tok1 * 1024 + col]     = pack_split(o[nf][2] * i1);
        ctx2[tok1 * 1024 + col + 1] = pack_split(o[nf][3] * i1);
    }
}

// ---------------- host launch ----------------
template <typename T>
static void* symaddr(T& sym) { void* p = nullptr; cudaGetSymbolAddress(&p, sym); return p; }

extern "C" void kernel_launch(void* const* d_in, const int* in_sizes, int n_in,
                              void* d_out, int out_size) {
    const float* src       = (const float*)d_in[0];
    const float* pos       = (const float*)d_in[1];
    const float* in_proj_w = (const float*)d_in[2];
    const float* alpha_in  = (const float*)d_in[3];
    const float* out_proj_w= (const float*)d_in[4];
    const float* alpha_out = (const float*)d_in[5];
    const float* w1        = (const float*)d_in[6];
    const float* b1        = (const float*)d_in[7];
    const float* alpha1    = (const float*)d_in[8];
    const float* w2        = (const float*)d_in[9];
    const float* b2        = (const float*)d_in[10];
    const float* alpha2    = (const float*)d_in[11];
    const float* ln1g      = (const float*)d_in[12];
    const float* ln1b      = (const float*)d_in[13];
    const float* ln2g      = (const float*)d_in[14];
    const float* ln2b      = (const float*)d_in[15];
    float* out = (float*)d_out;

    __nv_bfloat16* p_qk2  = (__nv_bfloat16*)symaddr(g_qk2);
    __nv_bfloat16* p_sv2  = (__nv_bfloat16*)symaddr(g_sv2);
    __nv_bfloat16* p_ctx2 = (__nv_bfloat16*)symaddr(g_ctx2);
    __nv_bfloat16* p_s2b2 = (__nv_bfloat16*)symaddr(g_s2b2);
    __nv_bfloat16* p_h2   = (__nv_bfloat16*)symaddr(g_h2);
    __nv_bfloat16* p_win2 = (__nv_bfloat16*)symaddr(g_win2);
    __nv_bfloat16* p_wout2= (__nv_bfloat16*)symaddr(g_wout2);
    __nv_bfloat16* p_w12  = (__nv_bfloat16*)symaddr(g_w12);
    __nv_bfloat16* p_w22  = (__nv_bfloat16*)symaddr(g_w22);
    uint*  p_qkp = (uint*)symaddr(g_qkp);
    uint*  p_vp  = (uint*)symaddr(g_vp);
    float* p_x   = (float*)symaddr(g_x);

    // idempotent; called every time (no static state allowed in kernel_launch)
    cudaFuncSetAttribute(flash_attn, cudaFuncAttributeMaxDynamicSharedMemorySize,
                         FLASH_SMEM);

    // 1) weights -> duplicated integer codes
    {
        int n4;
        n4 = (3 * D_ * D_) / 4;
        quant_dup<<<(n4 + 255) / 256, 256>>>((const float4*)in_proj_w, alpha_in, (uint4*)p_win2, n4);
        n4 = (D_ * D_) / 4;
        quant_dup<<<(n4 + 255) / 256, 256>>>((const float4*)out_proj_w, alpha_out, (uint4*)p_wout2, n4);
        n4 = (DFF_ * D_) / 4;
        quant_dup<<<(n4 + 255) / 256, 256>>>((const float4*)w1, alpha1, (uint4*)p_w12, n4);
        n4 = (D_ * DFF_) / 4;
        quant_dup<<<(n4 + 255) / 256, 256>>>((const float4*)w2, alpha2, (uint4*)p_w22, n4);
    }

    // 2) LN1 -> split(src2) and split(src2+pos)
    ln_kernel<<<NTOK, 256>>>(src, pos, ln1g, ln1b, (uint*)p_sv2, (uint*)p_qk2);

    // 3) [q|k] packed split; v packed split
    gemm_bf16<<<dim3(16, 32), 256>>>(NTOK, 2048, 2048,
        p_qk2, p_win2, alpha_in, nullptr, nullptr, nullptr, p_qkp, 0);
    gemm_bf16<<<dim3(8, 32), 256>>>(NTOK, 1024, 2048,
        p_sv2, p_win2 + (long long)2048 * 2048, alpha_in, nullptr, nullptr, nullptr, p_vp, 0);

    // 4-6) fused attention -> ctx packed split
    flash_attn<<<dim3(8, 64), 256, FLASH_SMEM>>>(p_qkp, p_vp, (uint*)p_ctx2);

    // 7) x = ctx2 @ wout2^T * alpha_out + src
    gemm_bf16<<<dim3(8, 32), 256>>>(NTOK, 1024, 2048,
        p_ctx2, p_wout2, alpha_out, nullptr, src, p_x, nullptr, 0);

    // 8) LN2 -> split(src2b)
    ln_kernel<<<NTOK, 256>>>(p_x, nullptr, ln2g, ln2b, (uint*)p_s2b2, nullptr);

    // 9) h2 = split(relu(s2b2 @ w12^T * alpha1 + b1))
    gemm_bf16<<<dim3(32, 32), 256>>>(NTOK, 4096, 2048,
        p_s2b2, p_w12, alpha1, b1, nullptr, nullptr, (uint*)p_h2, 1);

    // 10) out = h2 @ w22^T * alpha2 + b2 + x
    gemm_bf16<<<dim3(8, 32), 256>>>(NTOK, 1024, 8192,
        p_h2, p_w22, alpha2, b2, p_x, out, nullptr, 0);
}